// round 16
// baseline (speedup 1.0000x reference)
#include <cuda_runtime.h>

#define NN 50000
#define MM 800000
#define HH 64
#define EE 8
#define INN 16
#define DIN 137  // 1 + 2*H + E
#define LL 2

typedef unsigned long long u64;
typedef unsigned int u32;

// ---------------- device scratch (no allocs allowed) ----------------
__device__ float g_h0[NN * HH];
__device__ float g_h1[NN * HH];
__device__ float4 g_x4[NN];        // packed positions (w unused)
__device__ float g_aggmsg[NN * HH];
__device__ float g_aggf[NN * 4];
__device__ float g_cnt[NN];
__device__ float g_A[NN * HH];     // h @ W1[1:65] + b1
__device__ float g_B[NN * HH];     // h @ W1[65:129]

__device__ __forceinline__ float silu_f(float v) {
    return __fdividef(v, 1.0f + __expf(-v));
}
__device__ __forceinline__ u64 pack2(float s) {
    u64 r; asm("mov.b64 %0, {%1, %1};" : "=l"(r) : "f"(s)); return r;
}
__device__ __forceinline__ u64 packf2(float lo, float hi) {
    u64 r; asm("mov.b64 %0, {%1, %2};" : "=l"(r) : "f"(lo), "f"(hi)); return r;
}
__device__ __forceinline__ void unpack2(u64 v, float& lo, float& hi) {
    asm("mov.b64 {%0, %1}, %2;" : "=f"(lo), "=f"(hi) : "l"(v));
}
__device__ __forceinline__ void fma2(u64& acc, u64 w, u64 s) {
    asm("fma.rn.f32x2 %0, %1, %2, %0;" : "+l"(acc) : "l"(w), "l"(s));
}
__device__ __forceinline__ void add2(u64& acc, u64 v) {
    asm("add.rn.f32x2 %0, %1, %0;" : "+l"(acc) : "l"(v));
}
__device__ __forceinline__ void red4(float* p, float a, float b, float c, float d) {
    asm volatile("red.global.add.v4.f32 [%0], {%1, %2, %3, %4};"
                 :: "l"(p), "f"(a), "f"(b), "f"(c), "f"(d) : "memory");
}

// ---- quad helpers (k_node / embed) : lane h owns j = 16c+4h+o
__device__ __forceinline__ void fmaQuad(u64* a0, u64* a1, u64* a2, u64* a3,
                                        u64 s0, u64 s1, u64 s2, u64 s3,
                                        const float* wh) {
#pragma unroll
    for (int c = 0; c < 4; c++) {
        ulonglong2 t = *reinterpret_cast<const ulonglong2*>(wh + (c << 4));
        fma2(a0[2 * c], t.x, s0); fma2(a0[2 * c + 1], t.y, s0);
        fma2(a1[2 * c], t.x, s1); fma2(a1[2 * c + 1], t.y, s1);
        fma2(a2[2 * c], t.x, s2); fma2(a2[2 * c + 1], t.y, s2);
        fma2(a3[2 * c], t.x, s3); fma2(a3[2 * c + 1], t.y, s3);
    }
}
__device__ __forceinline__ void loadQuarterN(u64* a, const float* b, int h) {
#pragma unroll
    for (int c = 0; c < 4; c++) {
        ulonglong2 v = *reinterpret_cast<const ulonglong2*>(b + (h << 2) + (c << 4));
        a[2 * c] = v.x; a[2 * c + 1] = v.y;
    }
}
__device__ __forceinline__ void siluQuarter(const u64* a, float* f) {
#pragma unroll
    for (int m = 0; m < 8; m++) {
        float x, y; unpack2(a[m], x, y);
        f[2 * m] = silu_f(x); f[2 * m + 1] = silu_f(y);
    }
}
// ---- broadcast helpers
__device__ __forceinline__ void fmaB(u64* acc, u64 s2, const float* w) {
    const ulonglong2* w2 = reinterpret_cast<const ulonglong2*>(w);
#pragma unroll
    for (int q = 0; q < 16; q++) {
        ulonglong2 t = w2[q];
        fma2(acc[2 * q], t.x, s2); fma2(acc[2 * q + 1], t.y, s2);
    }
}
__device__ __forceinline__ void loadB(u64* acc, const float* b) {
    const ulonglong2* p = reinterpret_cast<const ulonglong2*>(b);
#pragma unroll
    for (int q = 0; q < 16; q++) {
        ulonglong2 v = p[q];
        acc[2 * q] = v.x; acc[2 * q + 1] = v.y;
    }
}
__device__ __forceinline__ void storeB(float* dst, const u64* acc) {
    ulonglong2* p = (ulonglong2*)dst;
#pragma unroll
    for (int q = 0; q < 16; q++)
        p[q] = make_ulonglong2(acc[2 * q], acc[2 * q + 1]);
}

// ---------------- init kernels ----------------
__global__ void k_cnt(const int* __restrict__ row) {
    int e = blockIdx.x * blockDim.x + threadIdx.x;
    if (e < MM) atomicAdd(&g_cnt[row[e]], 1.0f);
}
__global__ void k_packx(const float* __restrict__ x) {
    int n = blockIdx.x * blockDim.x + threadIdx.x;
    if (n < NN)
        g_x4[n] = make_float4(x[n * 3], x[n * 3 + 1], x[n * 3 + 2], 0.0f);
}

// -------- fused embedding + layer-0 A/B precompute --------
#define PREEMB_SMEM_FLOATS (INN * HH + 2 * HH * HH + 2 * HH)
__global__ __launch_bounds__(128) void k_embed_pre(
    const float* __restrict__ h_in,
    const float* __restrict__ embW, const float* __restrict__ embB,
    const float* __restrict__ W1, const float* __restrict__ B1) {
    extern __shared__ float sm[];
    float* sWe = sm;
    float* sWa = sWe + INN * HH;
    float* sWb = sWa + HH * HH;
    float* sbe = sWb + HH * HH;
    float* sb1 = sbe + HH;
    const int t = threadIdx.x;
    for (int i = t; i < INN * HH; i += 128) sWe[i] = embW[i];
    for (int i = t; i < HH * HH; i += 128) {
        sWa[i] = W1[(1 + (i >> 6)) * HH + (i & 63)];
        sWb[i] = W1[(1 + HH + (i >> 6)) * HH + (i & 63)];
    }
    for (int i = t; i < HH; i += 128) { sbe[i] = embB[i]; sb1[i] = B1[i]; }
    __syncthreads();
    int n = blockIdx.x * 128 + t;
    if (n >= NN) return;
    u64 acc[32];
    loadB(acc, sbe);
    const float4* hv4 = (const float4*)(h_in + (size_t)n * INN);
#pragma unroll
    for (int q = 0; q < INN / 4; q++) {
        float4 v = hv4[q];
        fmaB(acc, pack2(v.x), sWe + (4 * q + 0) * HH);
        fmaB(acc, pack2(v.y), sWe + (4 * q + 1) * HH);
        fmaB(acc, pack2(v.z), sWe + (4 * q + 2) * HH);
        fmaB(acc, pack2(v.w), sWe + (4 * q + 3) * HH);
    }
    storeB(g_h0 + (size_t)n * HH, acc);
    float hv[HH];
#pragma unroll
    for (int q = 0; q < 32; q++) unpack2(acc[q], hv[2 * q], hv[2 * q + 1]);
    loadB(acc, sb1);
#pragma unroll
    for (int k = 0; k < HH; k++) fmaB(acc, pack2(hv[k]), sWa + k * HH);
    storeB(g_A + (size_t)n * HH, acc);
#pragma unroll
    for (int q = 0; q < 32; q++) acc[q] = 0ull;
#pragma unroll
    for (int k = 0; k < HH; k++) fmaB(acc, pack2(hv[k]), sWb + k * HH);
    storeB(g_B + (size_t)n * HH, acc);
}

// ---------------- per-node precompute (layer >= 1) ----------------
#define PRE_SMEM_FLOATS (2 * HH * HH + HH)
__global__ __launch_bounds__(128) void k_pre(const float* __restrict__ h_in,
                                             const float* __restrict__ W1,
                                             const float* __restrict__ B1) {
    extern __shared__ float sm[];
    float* sWa = sm;
    float* sWb = sWa + HH * HH;
    float* sb  = sWb + HH * HH;
    const int t = threadIdx.x;
    for (int i = t; i < HH * HH; i += 128) {
        sWa[i] = W1[(1 + (i >> 6)) * HH + (i & 63)];
        sWb[i] = W1[(1 + HH + (i >> 6)) * HH + (i & 63)];
    }
    for (int i = t; i < HH; i += 128) sb[i] = B1[i];
    __syncthreads();
    int n = blockIdx.x * 128 + t;
    if (n >= NN) return;
    float hv[HH];
    {
        const float4* p = (const float4*)(h_in + (size_t)n * HH);
#pragma unroll
        for (int q = 0; q < 16; q++) {
            float4 v = p[q];
            hv[4 * q] = v.x; hv[4 * q + 1] = v.y;
            hv[4 * q + 2] = v.z; hv[4 * q + 3] = v.w;
        }
    }
    u64 acc[32];
    loadB(acc, sb);
#pragma unroll
    for (int k = 0; k < HH; k++) fmaB(acc, pack2(hv[k]), sWa + k * HH);
    storeB(g_A + (size_t)n * HH, acc);
#pragma unroll
    for (int q = 0; q < 32; q++) acc[q] = 0ull;
#pragma unroll
    for (int k = 0; k < HH; k++) fmaB(acc, pack2(hv[k]), sWb + k * HH);
    storeB(g_B + (size_t)n * HH, acc);
}

// ===== edge kernel: OCT-split (8 lanes/edge-group, 8 edges/group) =========
// lane o owns outputs j in {4o + 32c + t}, c=0..1, t=0..3
#define EDGE_SMEM_FLOATS (9 * HH + 2 * HH * HH + 3 * HH + 4 + 8 * HH * 32)

__global__ __launch_bounds__(256, 2) void k_edge(
    const int* __restrict__ row, const int* __restrict__ col,
    const float* __restrict__ efea,
    const float* __restrict__ W1,
    const float* __restrict__ W2, const float* __restrict__ B2,
    const float* __restrict__ CW1, const float* __restrict__ CB1,
    const float* __restrict__ CW2, const float* __restrict__ CB2) {
    extern __shared__ float sm[];
    float* sW1e = sm;                  // [9][64] natural
    float* sW2p = sW1e + 9 * HH;       // [64][64] natural
    float* sCW1 = sW2p + HH * HH;      // [64][64] natural
    float* sB2  = sCW1 + HH * HH;
    float* sCB1 = sB2 + HH;
    float* sCW2 = sCB1 + HH;
    float* sCB2 = sCW2 + HH;
    float* sStg = sCB2 + 4;            // 8 warps * 64 rows * 32 floats

    const int t = threadIdx.x;
    for (int i = t; i < 9 * HH; i += 256) {
        int k = i >> 6, j = i & 63;
        int srcRow = (k == 0) ? 0 : (1 + 2 * HH + (k - 1));
        sW1e[i] = W1[srcRow * HH + j];
    }
    for (int i = t; i < HH * HH; i += 256) {
        sW2p[i] = W2[i];
        sCW1[i] = CW1[i];
    }
    for (int i = t; i < HH; i += 256) {
        sB2[i] = B2[i]; sCB1[i] = CB1[i]; sCW2[i] = CW2[i];
    }
    if (t == 0) sCB2[0] = CB2[0];
    __syncthreads();

    const int wid = t >> 5, lane = t & 31;
    const int g = lane >> 3, o = lane & 7;
    const int o4 = o << 2;
    float* stF = sStg + wid * (HH * 32);   // [64 rows][32 warp-edges]

    const int eB = blockIdx.x * 256 + (wid << 5) + (g << 3);  // group base edge
    const int eo = eB + o;                                    // own edge
    const int r_own = row[eo], c_own = col[eo];
    const float4 xr = g_x4[r_own], xc = g_x4[c_own];
    const float rx = xr.x - xc.x, ry = xr.y - xc.y, rz = xr.z - xc.z;
    const float r2 = rx * rx + ry * ry + rz * rz;
    const float4 efa = ((const float4*)efea)[(size_t)eo * 2];
    const float4 efb = ((const float4*)efea)[(size_t)eo * 2 + 1];

    // stage own-edge scalars: rows 0..8, col = lane (warp-edge index)
    stF[0 * 32 + lane] = r2;
    stF[1 * 32 + lane] = efa.x;
    stF[2 * 32 + lane] = efa.y;
    stF[3 * 32 + lane] = efa.z;
    stF[4 * 32 + lane] = efa.w;
    stF[5 * 32 + lane] = efb.x;
    stF[6 * 32 + lane] = efb.y;
    stF[7 * 32 + lane] = efb.z;
    stF[8 * 32 + lane] = efb.w;
    __syncwarp();

    // group's 8 edge endpoints
    const int4 rv0 = *(const int4*)(row + eB);
    const int4 rv1 = *(const int4*)(row + eB + 4);
    const int4 cv0 = *(const int4*)(col + eB);
    const int4 cv1 = *(const int4*)(col + eB + 4);
    const int re[8] = {rv0.x, rv0.y, rv0.z, rv0.w, rv1.x, rv1.y, rv1.z, rv1.w};
    const int ce[8] = {cv0.x, cv0.y, cv0.z, cv0.w, cv1.x, cv1.y, cv1.z, cv1.w};

    // acc[e*4 + 2c + m] : edge e, chunk c, u64 m
    u64 acc[32];

    // ---- stage 1: acc = A[r]+B[c]; += r2*w0; += ef @ Wef ----
#pragma unroll
    for (int e = 0; e < 8; e++) {
        const float* pa = g_A + (size_t)re[e] * HH + o4;
        const float* pb = g_B + (size_t)ce[e] * HH + o4;
#pragma unroll
        for (int c = 0; c < 2; c++) {
            ulonglong2 va = *(const ulonglong2*)(pa + (c << 5));
            ulonglong2 vb = *(const ulonglong2*)(pb + (c << 5));
            add2(va.x, vb.x); add2(va.y, vb.y);
            acc[e * 4 + 2 * c] = va.x;
            acc[e * 4 + 2 * c + 1] = va.y;
        }
    }
#pragma unroll
    for (int k = 0; k < 9; k++) {
        const float4 s03 = *(const float4*)(stF + k * 32 + (g << 3));
        const float4 s47 = *(const float4*)(stF + k * 32 + (g << 3) + 4);
        const float* wk = sW1e + (k << 6) + o4;
        const ulonglong2 w0 = *(const ulonglong2*)wk;
        const ulonglong2 w1 = *(const ulonglong2*)(wk + 32);
        const float sv[8] = {s03.x, s03.y, s03.z, s03.w, s47.x, s47.y, s47.z, s47.w};
#pragma unroll
        for (int e = 0; e < 8; e++) {
            const u64 p = pack2(sv[e]);
            fma2(acc[e * 4 + 0], w0.x, p);
            fma2(acc[e * 4 + 1], w0.y, p);
            fma2(acc[e * 4 + 2], w1.x, p);
            fma2(acc[e * 4 + 3], w1.y, p);
        }
    }
    // silu in place
#pragma unroll
    for (int m = 0; m < 32; m++) {
        float x, y; unpack2(acc[m], x, y);
        acc[m] = packf2(silu_f(x), silu_f(y));
    }
    __syncwarp();   // all scalar-stage reads done before overwrite
    // stage hid: row j = 4o + 32c + t, cols = warp edges; extract across e
#pragma unroll
    for (int c = 0; c < 2; c++)
#pragma unroll
        for (int tt = 0; tt < 4; tt++) {
            float v[8];
#pragma unroll
            for (int e = 0; e < 8; e++) {
                float x, y;
                unpack2(acc[e * 4 + 2 * c + (tt >> 1)], x, y);
                v[e] = (tt & 1) ? y : x;
            }
            float* dst = stF + (o4 + (c << 5) + tt) * 32 + (g << 3);
            *(float4*)dst = make_float4(v[0], v[1], v[2], v[3]);
            *(float4*)(dst + 4) = make_float4(v[4], v[5], v[6], v[7]);
        }
    __syncwarp();

    // ---- stage 2: msg = silu(hid @ W2 + b2) ----
    {
        const ulonglong2 b0 = *(const ulonglong2*)(sB2 + o4);
        const ulonglong2 b1 = *(const ulonglong2*)(sB2 + o4 + 32);
#pragma unroll
        for (int e = 0; e < 8; e++) {
            acc[e * 4 + 0] = b0.x; acc[e * 4 + 1] = b0.y;
            acc[e * 4 + 2] = b1.x; acc[e * 4 + 3] = b1.y;
        }
    }
#pragma unroll
    for (int k = 0; k < HH; k++) {
        const float4 s03 = *(const float4*)(stF + k * 32 + (g << 3));
        const float4 s47 = *(const float4*)(stF + k * 32 + (g << 3) + 4);
        const float* wk = sW2p + (k << 6) + o4;
        const ulonglong2 w0 = *(const ulonglong2*)wk;
        const ulonglong2 w1 = *(const ulonglong2*)(wk + 32);
        const float sv[8] = {s03.x, s03.y, s03.z, s03.w, s47.x, s47.y, s47.z, s47.w};
#pragma unroll
        for (int e = 0; e < 8; e++) {
            const u64 p = pack2(sv[e]);
            fma2(acc[e * 4 + 0], w0.x, p);
            fma2(acc[e * 4 + 1], w0.y, p);
            fma2(acc[e * 4 + 2], w1.x, p);
            fma2(acc[e * 4 + 3], w1.y, p);
        }
    }
#pragma unroll
    for (int m = 0; m < 32; m++) {
        float x, y; unpack2(acc[m], x, y);
        acc[m] = packf2(silu_f(x), silu_f(y));
    }
    // msg atomics: per edge, 2 red4 at offsets 4o and 4o+32
#pragma unroll
    for (int e = 0; e < 8; e++) {
        float* am = g_aggmsg + (size_t)re[e] * HH;
#pragma unroll
        for (int c = 0; c < 2; c++) {
            float x0, y0, x1, y1;
            unpack2(acc[e * 4 + 2 * c], x0, y0);
            unpack2(acc[e * 4 + 2 * c + 1], x1, y1);
            red4(am + o4 + (c << 5), x0, y0, x1, y1);
        }
    }
    __syncwarp();   // stage-2 hid reads done before msg overwrite
#pragma unroll
    for (int c = 0; c < 2; c++)
#pragma unroll
        for (int tt = 0; tt < 4; tt++) {
            float v[8];
#pragma unroll
            for (int e = 0; e < 8; e++) {
                float x, y;
                unpack2(acc[e * 4 + 2 * c + (tt >> 1)], x, y);
                v[e] = (tt & 1) ? y : x;
            }
            float* dst = stF + (o4 + (c << 5) + tt) * 32 + (g << 3);
            *(float4*)dst = make_float4(v[0], v[1], v[2], v[3]);
            *(float4*)(dst + 4) = make_float4(v[4], v[5], v[6], v[7]);
        }
    __syncwarp();

    // ---- stage 3: cm = silu(msg @ CW1 + cb1) . CW2 + cb2 ----
    {
        const ulonglong2 b0 = *(const ulonglong2*)(sCB1 + o4);
        const ulonglong2 b1 = *(const ulonglong2*)(sCB1 + o4 + 32);
#pragma unroll
        for (int e = 0; e < 8; e++) {
            acc[e * 4 + 0] = b0.x; acc[e * 4 + 1] = b0.y;
            acc[e * 4 + 2] = b1.x; acc[e * 4 + 3] = b1.y;
        }
    }
#pragma unroll
    for (int k = 0; k < HH; k++) {
        const float4 s03 = *(const float4*)(stF + k * 32 + (g << 3));
        const float4 s47 = *(const float4*)(stF + k * 32 + (g << 3) + 4);
        const float* wk = sCW1 + (k << 6) + o4;
        const ulonglong2 w0 = *(const ulonglong2*)wk;
        const ulonglong2 w1 = *(const ulonglong2*)(wk + 32);
        const float sv[8] = {s03.x, s03.y, s03.z, s03.w, s47.x, s47.y, s47.z, s47.w};
#pragma unroll
        for (int e = 0; e < 8; e++) {
            const u64 p = pack2(sv[e]);
            fma2(acc[e * 4 + 0], w0.x, p);
            fma2(acc[e * 4 + 1], w0.y, p);
            fma2(acc[e * 4 + 2], w1.x, p);
            fma2(acc[e * 4 + 3], w1.y, p);
        }
    }
    // partial dot with CW2 over lane's 8 outputs
    float part[8];
    {
        const float4 w2a = *(const float4*)(sCW2 + o4);
        const float4 w2b = *(const float4*)(sCW2 + o4 + 32);
        const float wa[8] = {w2a.x, w2a.y, w2a.z, w2a.w, w2b.x, w2b.y, w2b.z, w2b.w};
#pragma unroll
        for (int e = 0; e < 8; e++) {
            float s = 0.0f;
#pragma unroll
            for (int m = 0; m < 4; m++) {
                float x, y;
                unpack2(acc[e * 4 + m], x, y);
                const int jb = ((m >> 1) << 2) + ((m & 1) << 1);
                s += silu_f(x) * wa[jb] + silu_f(y) * wa[jb + 1];
            }
            part[e] = s;
        }
    }
    __syncwarp();   // stage-3 msg reads done
    // partial reduce via rows 0..7: row e, col lane
#pragma unroll
    for (int e = 0; e < 8; e++) stF[e * 32 + lane] = part[e];
    __syncwarp();
    {
        const float4 q0 = *(const float4*)(stF + o * 32 + (g << 3));
        const float4 q1 = *(const float4*)(stF + o * 32 + (g << 3) + 4);
        float cm = q0.x + q0.y + q0.z + q0.w + q1.x + q1.y + q1.z + q1.w + sCB2[0];
        red4(&g_aggf[(size_t)r_own * 4], rx * cm, ry * cm, rz * cm, 0.0f);
    }
}

// ---------------- node kernel: QUAD-split, natural layout ----------------
#define NODE_SMEM_FLOATS (2 * HH * HH + HH * HH + 2 * HH)
__global__ __launch_bounds__(128, 3) void k_node(
    const float* __restrict__ h_in, float* __restrict__ h_out,
    const float* __restrict__ NW1, const float* __restrict__ NB1,
    const float* __restrict__ NW2, const float* __restrict__ NB2,
    float* __restrict__ out_x, float* __restrict__ out_h, int writeOut) {
    extern __shared__ float sm[];
    float* sW1 = sm;                  // [128][64] natural
    float* sW2 = sW1 + 2 * HH * HH;   // [64][64] natural
    float* sB1 = sW2 + HH * HH;
    float* sB2 = sB1 + HH;
    const int t = threadIdx.x;
    for (int i = t; i < 2 * HH * HH; i += 128) sW1[i] = NW1[i];
    for (int i = t; i < HH * HH; i += 128) sW2[i] = NW2[i];
    for (int i = t; i < HH; i += 128) { sB1[i] = NB1[i]; sB2[i] = NB2[i]; }
    __syncthreads();

    const int wid = t >> 5, lane = t & 31;
    const int h = lane & 3, qd = lane >> 2, h4 = h << 2;
    int n0 = blockIdx.x * 128 + (wid << 5) + (qd << 2);
    if (n0 + 3 >= NN) n0 = NN - 4;

    u64 a0[8], a1[8], a2[8], a3[8];
    loadQuarterN(a0, sB1, h);
#pragma unroll
    for (int m = 0; m < 8; m++) { a1[m] = a0[m]; a2[m] = a0[m]; a3[m] = a0[m]; }
    {
        const float4* p0 = (const float4*)(h_in + (size_t)n0 * HH);
        const float4* p1 = (const float4*)(h_in + (size_t)(n0 + 1) * HH);
        const float4* p2 = (const float4*)(h_in + (size_t)(n0 + 2) * HH);
        const float4* p3 = (const float4*)(h_in + (size_t)(n0 + 3) * HH);
#pragma unroll
        for (int q = 0; q < 16; q++) {
            float4 u0 = p0[q], u1 = p1[q], u2 = p2[q], u3 = p3[q];
            fmaQuad(a0, a1, a2, a3, pack2(u0.x), pack2(u1.x), pack2(u2.x), pack2(u3.x),
                    sW1 + ((4 * q + 0) << 6) + h4);
            fmaQuad(a0, a1, a2, a3, pack2(u0.y), pack2(u1.y), pack2(u2.y), pack2(u3.y),
                    sW1 + ((4 * q + 1) << 6) + h4);
            fmaQuad(a0, a1, a2, a3, pack2(u0.z), pack2(u1.z), pack2(u2.z), pack2(u3.z),
                    sW1 + ((4 * q + 2) << 6) + h4);
            fmaQuad(a0, a1, a2, a3, pack2(u0.w), pack2(u1.w), pack2(u2.w), pack2(u3.w),
                    sW1 + ((4 * q + 3) << 6) + h4);
        }
        const float4* m0 = (const float4*)(g_aggmsg + (size_t)n0 * HH);
        const float4* m1 = (const float4*)(g_aggmsg + (size_t)(n0 + 1) * HH);
        const float4* m2 = (const float4*)(g_aggmsg + (size_t)(n0 + 2) * HH);
        const float4* m3 = (const float4*)(g_aggmsg + (size_t)(n0 + 3) * HH);
#pragma unroll
        for (int q = 0; q < 16; q++) {
            float4 u0 = m0[q], u1 = m1[q], u2 = m2[q], u3 = m3[q];
            fmaQuad(a0, a1, a2, a3, pack2(u0.x), pack2(u1.x), pack2(u2.x), pack2(u3.x),
                    sW1 + ((HH + 4 * q + 0) << 6) + h4);
            fmaQuad(a0, a1, a2, a3, pack2(u0.y), pack2(u1.y), pack2(u2.y), pack2(u3.y),
                    sW1 + ((HH + 4 * q + 1) << 6) + h4);
            fmaQuad(a0, a1, a2, a3, pack2(u0.z), pack2(u1.z), pack2(u2.z), pack2(u3.z),
                    sW1 + ((HH + 4 * q + 2) << 6) + h4);
            fmaQuad(a0, a1, a2, a3, pack2(u0.w), pack2(u1.w), pack2(u2.w), pack2(u3.w),
                    sW1 + ((HH + 4 * q + 3) << 6) + h4);
        }
    }
    float hid0[16], hid1[16], hid2[16], hid3[16];
    siluQuarter(a0, hid0);
    siluQuarter(a1, hid1);
    siluQuarter(a2, hid2);
    siluQuarter(a3, hid3);

    loadQuarterN(a0, sB2, h);
#pragma unroll
    for (int m = 0; m < 8; m++) { a1[m] = a0[m]; a2[m] = a0[m]; a3[m] = a0[m]; }
#pragma unroll
    for (int k = 0; k < HH; k++) {
        const int src = (lane & ~3) | ((k >> 2) & 3);
        const int mi = ((k >> 4) << 2) + (k & 3);
        float s0 = __shfl_sync(0xffffffffu, hid0[mi], src);
        float s1 = __shfl_sync(0xffffffffu, hid1[mi], src);
        float s2 = __shfl_sync(0xffffffffu, hid2[mi], src);
        float s3 = __shfl_sync(0xffffffffu, hid3[mi], src);
        fmaQuad(a0, a1, a2, a3, pack2(s0), pack2(s1), pack2(s2), pack2(s3),
                sW2 + (k << 6) + h4);
    }

    {
        float* base = writeOut ? out_h : h_out;
        const u64* as[4] = {a0, a1, a2, a3};
#pragma unroll
        for (int i = 0; i < 4; i++) {
            float* dst = base + (size_t)(n0 + i) * HH + h4;
#pragma unroll
            for (int c = 0; c < 4; c++) {
                float x0, y0, x1, y1;
                unpack2(as[i][2 * c], x0, y0);
                unpack2(as[i][2 * c + 1], x1, y1);
                *(float4*)(dst + (c << 4)) = make_float4(x0, y0, x1, y1);
            }
        }
    }
    {
        const int n = n0 + h;
        float cnt = g_cnt[n];
        float inv = 1.0f / fmaxf(cnt, 1.0f);
        float4 xp = g_x4[n];
        float4 af = *(float4*)&g_aggf[(size_t)n * 4];
        float tx = fminf(fmaxf(af.x * inv, -100.0f), 100.0f);
        float ty = fminf(fmaxf(af.y * inv, -100.0f), 100.0f);
        float tz = fminf(fmaxf(af.z * inv, -100.0f), 100.0f);
        xp.x += tx; xp.y += ty; xp.z += tz;
        g_x4[n] = xp;
        if (writeOut) {
            out_x[n * 3 + 0] = xp.x;
            out_x[n * 3 + 1] = xp.y;
            out_x[n * 3 + 2] = xp.z;
        }
    }
}

// ---------------- launch ----------------
extern "C" void kernel_launch(void* const* d_in, const int* in_sizes, int n_in,
                              void* d_out, int out_size) {
    const float* x    = (const float*)d_in[0];
    const float* h    = (const float*)d_in[1];
    const int*   row  = (const int*)d_in[2];
    const int*   col  = (const int*)d_in[3];
    const float* efea = (const float*)d_in[4];
    const float* embW = (const float*)d_in[5];
    const float* embB = (const float*)d_in[6];
    const float* eW1  = (const float*)d_in[7];
    const float* eB1  = (const float*)d_in[8];
    const float* eW2  = (const float*)d_in[9];
    const float* eB2  = (const float*)d_in[10];
    const float* cW1  = (const float*)d_in[11];
    const float* cB1  = (const float*)d_in[12];
    const float* cW2  = (const float*)d_in[13];
    const float* cB2  = (const float*)d_in[14];
    const float* nW1  = (const float*)d_in[15];
    const float* nB1  = (const float*)d_in[16];
    const float* nW2  = (const float*)d_in[17];
    const float* nB2  = (const float*)d_in[18];
    float* out = (float*)d_out;

    void *p_h0, *p_h1, *p_am, *p_af, *p_cnt;
    cudaGetSymbolAddress(&p_h0, g_h0);
    cudaGetSymbolAddress(&p_h1, g_h1);
    cudaGetSymbolAddress(&p_am, g_aggmsg);
    cudaGetSymbolAddress(&p_af, g_aggf);
    cudaGetSymbolAddress(&p_cnt, g_cnt);

    const int edge_smem   = EDGE_SMEM_FLOATS * sizeof(float);
    const int node_smem   = NODE_SMEM_FLOATS * sizeof(float);
    const int pre_smem    = PRE_SMEM_FLOATS * sizeof(float);
    const int preemb_smem = PREEMB_SMEM_FLOATS * sizeof(float);
    cudaFuncSetAttribute(k_edge, cudaFuncAttributeMaxDynamicSharedMemorySize, edge_smem);
    cudaFuncSetAttribute(k_node, cudaFuncAttributeMaxDynamicSharedMemorySize, node_smem);
    cudaFuncSetAttribute(k_pre,  cudaFuncAttributeMaxDynamicSharedMemorySize, pre_smem);
    cudaFuncSetAttribute(k_embed_pre, cudaFuncAttributeMaxDynamicSharedMemorySize, preemb_smem);

    cudaMemsetAsync(p_cnt, 0, NN * sizeof(float), 0);
    k_packx<<<(NN + 255) / 256, 256>>>(x);
    k_cnt<<<(MM + 255) / 256, 256>>>(row);
    k_embed_pre<<<(NN + 127) / 128, 128, preemb_smem>>>(h, embW, embB, eW1, eB1);

    float* hbuf[2] = {(float*)p_h0, (float*)p_h1};
    float* out_x = out;
    float* out_h = out + (size_t)NN * 3;
    const int node_grid = (NN + 127) / 128;   // 391

    for (int i = 0; i < LL; i++) {
        cudaMemsetAsync(p_am, 0, (size_t)NN * HH * sizeof(float), 0);
        cudaMemsetAsync(p_af, 0, (size_t)NN * 4 * sizeof(float), 0);
        if (i > 0)
            k_pre<<<(NN + 127) / 128, 128, pre_smem>>>(
                hbuf[i & 1], eW1 + (size_t)i * DIN * HH, eB1 + (size_t)i * HH);
        k_edge<<<MM / 256, 256, edge_smem>>>(
            row, col, efea,
            eW1 + (size_t)i * DIN * HH,
            eW2 + (size_t)i * HH * HH,  eB2 + (size_t)i * HH,
            cW1 + (size_t)i * HH * HH,  cB1 + (size_t)i * HH,
            cW2 + (size_t)i * HH,       cB2 + (size_t)i * 1);
        k_node<<<node_grid, 128, node_smem>>>(
            hbuf[i & 1], hbuf[(i + 1) & 1],
            nW1 + (size_t)i * 2 * HH * HH, nB1 + (size_t)i * HH,
            nW2 + (size_t)i * HH * HH,     nB2 + (size_t)i * HH,
            out_x, out_h, (i == LL - 1) ? 1 : 0);
    }
    (void)in_sizes; (void)n_in; (void)out_size;
}